// round 9
// baseline (speedup 1.0000x reference)
#include <cuda_runtime.h>
#include <cuda_bf16.h>
#include <cstdint>

#define D_FEAT 64
#define TILE_M 128
#define NTHREADS 256
#define INV_T 10.0f
#define LOG2E 1.4426950408889634f
#define HALF_K 256
#define MAXTILES 7

// smem byte offsets
#define SM_G1 0            // GEMM1 B fragments, packed   64KB
#define SM_G2 65536        // GEMM2 B fragments, packed   64KB
#define SM_BIAS 131072     // 256 floats                  1KB
#define SM_SSUM 132096     // MAXTILES*128 floats         3.5KB
#define SM_TOTAL 135680

typedef unsigned int u32;

__device__ __forceinline__ u32 s2u(const void* p) {
    u32 a;
    asm("{ .reg .u64 t; cvta.to.shared.u64 t, %1; cvt.u32.u64 %0, t; }" : "=r"(a) : "l"(p));
    return a;
}
__device__ __forceinline__ void lds128(u32 addr, u32& q0, u32& q1, u32& q2, u32& q3) {
    asm volatile("ld.shared.v4.b32 {%0,%1,%2,%3}, [%4];"
                 : "=r"(q0), "=r"(q1), "=r"(q2), "=r"(q3) : "r"(addr));
}
__device__ __forceinline__ float ex2f(float v) {
    float y; asm("ex2.approx.ftz.f32 %0, %1;" : "=f"(y) : "f"(v)); return y;
}
// pack (lo, hi) -> bf16x2 with lo in low half
__device__ __forceinline__ u32 bf2(float lo, float hi) {
    u32 r; asm("cvt.rn.satfinite.bf16x2.f32 %0, %1, %2;" : "=r"(r) : "f"(hi), "f"(lo)); return r;
}
__device__ __forceinline__ float2 unbf2(u32 v) {
    __nv_bfloat162 b = *reinterpret_cast<__nv_bfloat162*>(&v);
    return make_float2(__bfloat162float(b.x), __bfloat162float(b.y));
}
// hi split + residual lo split
__device__ __forceinline__ u32 bf2r(float a, float b, u32& lo) {
    const u32 h = bf2(a, b);
    const float2 f = unbf2(h);
    lo = bf2(a - f.x, b - f.y);
    return h;
}
// D += A*B, m16n8k16 bf16 -> f32
__device__ __forceinline__ void mma16816(float* d, const u32* a, u32 b0, u32 b1) {
    asm volatile("mma.sync.aligned.m16n8k16.row.col.f32.bf16.bf16.f32 "
                 "{%0,%1,%2,%3}, {%4,%5,%6,%7}, {%8,%9}, {%0,%1,%2,%3};"
                 : "+f"(d[0]), "+f"(d[1]), "+f"(d[2]), "+f"(d[3])
                 : "r"(a[0]), "r"(a[1]), "r"(a[2]), "r"(a[3]), "r"(b0), "r"(b1));
}

__global__ void __launch_bounds__(NTHREADS, 1)
kmeans_hmma6_kernel(const float* __restrict__ x,
                    const float* __restrict__ centroids,
                    float* __restrict__ out,
                    int n_tiles)
{
    extern __shared__ char smem[];
    const u32 sb = s2u(smem);
    const int tid = threadIdx.x;
    const int lane = tid & 31;
    const int wid = tid >> 5;
    const int gid = lane >> 2;
    const int tg = lane & 3;
    const int m0 = wid * 16;
    // phase rotation: warps sharing an SMSP (w, w+4) get different phases,
    // all 4 phases uniformly occupied across the CTA
    const int rot = ((wid & 3) + ((wid >> 2) << 1)) & 3;

    const float SC = 2.0f * INV_T * LOG2E;
    const u32 g1b = sb + SM_G1 + (u32)lane * 16;
    const u32 g2b = sb + SM_G2 + (u32)lane * 16;

    #pragma unroll 1
    for (int h = 0; h < 2; h++) {
        __syncthreads();
        // ---- build half h: fragment-packed B tables for both GEMMs + bias ----
        {
            const float4* C4 = reinterpret_cast<const float4*>(centroids) +
                               (size_t)h * HALF_K * (D_FEAT / 4);
            const float BSCALE = INV_T * LOG2E;
            #pragma unroll 1
            for (int it = 0; it < 16; it++) {
                const int i = tid + it * NTHREADS;     // 0..4095
                const float4 v = C4[i];
                const int cl = i >> 4;                 // local cluster 0..255
                const int dq = i & 15;                 // float4 index in row
                float vf[4] = {v.x, v.y, v.z, v.w};
                // GEMM1 slot components for this cluster
                const int sub = cl >> 6, nb = (cl >> 3) & 7, gids = cl & 7;
                // GEMM2 slot components
                const int rr = cl & 63, t2 = rr >> 4, q2 = rr & 15;
                const int reg2 = (q2 >> 3) & 1, tgs2 = (q2 & 7) >> 1, el2 = q2 & 1;
                #pragma unroll
                for (int e = 0; e < 4; e++) {
                    const int d = 4 * dq + e;
                    u32 lo1;
                    const u32 hi1 = bf2r(vf[e], 0.f, lo1);   // low halves hold the bf16s
                    const __nv_bfloat162 H = *reinterpret_cast<const __nv_bfloat162*>(&hi1);
                    const __nv_bfloat162 L = *reinterpret_cast<const __nv_bfloat162*>(&lo1);
                    // G1: k = feat
                    {
                        const int s = d >> 4, r = d & 15;
                        const int reg = (r >> 3) & 1, tgs = (r & 7) >> 1, el = r & 1;
                        const u32 off = (u32)(((sub * 32 + s * 8 + nb) * 32 + gids * 4 + tgs) * 16
                                              + reg * 4 + el * 2);
                        *reinterpret_cast<__nv_bfloat16*>(smem + SM_G1 + off)     = H.x;
                        *reinterpret_cast<__nv_bfloat16*>(smem + SM_G1 + off + 8) = L.x;
                    }
                    // G2: k = cluster, n = feat
                    {
                        const int nb2 = d >> 3, gids2 = d & 7;
                        const u32 off = (u32)(((sub * 32 + t2 * 8 + nb2) * 32 + gids2 * 4 + tgs2) * 16
                                              + reg2 * 4 + el2 * 2);
                        *reinterpret_cast<__nv_bfloat16*>(smem + SM_G2 + off)     = H.x;
                        *reinterpret_cast<__nv_bfloat16*>(smem + SM_G2 + off + 8) = L.x;
                    }
                }
                // bias
                float p = v.x * v.x + v.y * v.y + v.z * v.z + v.w * v.w;
                p += __shfl_xor_sync(0xFFFFFFFF, p, 1);
                p += __shfl_xor_sync(0xFFFFFFFF, p, 2);
                p += __shfl_xor_sync(0xFFFFFFFF, p, 4);
                p += __shfl_xor_sync(0xFFFFFFFF, p, 8);
                if ((lane & 15) == 0)
                    *reinterpret_cast<float*>(smem + SM_BIAS + cl * 4) = p * BSCALE;
            }
        }
        __syncthreads();

        // ---- tile loop ----
        int tloc = 0;
        #pragma unroll 1
        for (int tile = blockIdx.x; tile < n_tiles; tile += gridDim.x, tloc++) {
            // A fragments from gmem (PTX spec positions)
            u32 Ah[4][4], Al[4][4];
            {
                const float* xb = x + ((size_t)tile * TILE_M + m0 + gid) * D_FEAT;
                #pragma unroll
                for (int s = 0; s < 4; s++) {
                    const int c0 = 16 * s + 2 * tg;
                    const float2 v0 = *reinterpret_cast<const float2*>(xb + c0);
                    const float2 v1 = *reinterpret_cast<const float2*>(xb + 8 * D_FEAT + c0);
                    const float2 v2 = *reinterpret_cast<const float2*>(xb + c0 + 8);
                    const float2 v3 = *reinterpret_cast<const float2*>(xb + 8 * D_FEAT + c0 + 8);
                    Ah[s][0] = bf2r(v0.x, v0.y, Al[s][0]);
                    Ah[s][1] = bf2r(v1.x, v1.y, Al[s][1]);
                    Ah[s][2] = bf2r(v2.x, v2.y, Al[s][2]);
                    Ah[s][3] = bf2r(v3.x, v3.y, Al[s][3]);
                }
            }

            float O[8][4];
            #pragma unroll
            for (int n = 0; n < 8; n++)
                #pragma unroll
                for (int e = 0; e < 4; e++) O[n][e] = 0.f;
            float sum0 = 0.f, sum1 = 0.f;

            #pragma unroll 1
            for (int i = 0; i < 4; i++) {        // 64-cluster sub-chunks, rotated
                const int sub = (i + rot) & 3;   // per-warp phase stagger
                float S[8][4];
                #pragma unroll
                for (int n = 0; n < 8; n++)
                    #pragma unroll
                    for (int e = 0; e < 4; e++) S[n][e] = 0.f;

                // GEMM1: 1x LDS.128 + 3 HMMA inner loop, zero address math
                #pragma unroll
                for (int s = 0; s < 4; s++) {
                    const u32 base = g1b + (u32)sub * 16384 + (u32)s * 4096;
                    #pragma unroll
                    for (int nb = 0; nb < 8; nb++) {
                        u32 q0, q1, q2, q3;
                        lds128(base + nb * 512, q0, q1, q2, q3);
                        mma16816(S[nb], Ah[s], q0, q1);
                        mma16816(S[nb], Ah[s], q2, q3);
                        mma16816(S[nb], Al[s], q0, q1);
                    }
                }

                // epilogue: logits -> weights
                #pragma unroll
                for (int nb = 0; nb < 8; nb++) {
                    const int coll = sub * 64 + nb * 8 + 2 * tg;
                    const float2 bb = *reinterpret_cast<const float2*>(smem + SM_BIAS + coll * 4);
                    S[nb][0] = ex2f(fmaf(S[nb][0], SC, -bb.x));
                    S[nb][1] = ex2f(fmaf(S[nb][1], SC, -bb.y));
                    S[nb][2] = ex2f(fmaf(S[nb][2], SC, -bb.x));
                    S[nb][3] = ex2f(fmaf(S[nb][3], SC, -bb.y));
                    sum0 += S[nb][0] + S[nb][1];
                    sum1 += S[nb][2] + S[nb][3];
                }

                // GEMM2: W-split + 1x LDS.128 + 3 HMMA inner loop
                #pragma unroll
                for (int t = 0; t < 4; t++) {
                    u32 Wh[4], Wl[4];
                    Wh[0] = bf2r(S[2*t][0],   S[2*t][1],   Wl[0]);
                    Wh[1] = bf2r(S[2*t][2],   S[2*t][3],   Wl[1]);
                    Wh[2] = bf2r(S[2*t+1][0], S[2*t+1][1], Wl[2]);
                    Wh[3] = bf2r(S[2*t+1][2], S[2*t+1][3], Wl[3]);
                    const u32 base = g2b + (u32)sub * 16384 + (u32)t * 4096;
                    #pragma unroll
                    for (int nb2 = 0; nb2 < 8; nb2++) {
                        u32 q0, q1, q2, q3;
                        lds128(base + nb2 * 512, q0, q1, q2, q3);
                        mma16816(O[nb2], Wh, q0, q1);
                        mma16816(O[nb2], Wh, q2, q3);
                        mma16816(O[nb2], Wl, q0, q1);
                    }
                }
            }

            // row sums across the 4 lanes of each row group
            sum0 += __shfl_xor_sync(0xFFFFFFFF, sum0, 1);
            sum0 += __shfl_xor_sync(0xFFFFFFFF, sum0, 2);
            sum1 += __shfl_xor_sync(0xFFFFFFFF, sum1, 1);
            sum1 += __shfl_xor_sync(0xFFFFFFFF, sum1, 2);

            float* op = out + ((size_t)tile * TILE_M) * D_FEAT;
            const int r0 = m0 + gid;
            const int r1 = r0 + 8;
            float* ss = reinterpret_cast<float*>(smem + SM_SSUM) + tloc * TILE_M;

            if (h == 0) {
                if (tg == 0) { ss[r0] = sum0; ss[r1] = sum1; }
                #pragma unroll
                for (int n = 0; n < 8; n++) {
                    const int col = 8 * n + 2 * tg;
                    *reinterpret_cast<float2*>(op + r0 * D_FEAT + col) = make_float2(O[n][0], O[n][1]);
                    *reinterpret_cast<float2*>(op + r1 * D_FEAT + col) = make_float2(O[n][2], O[n][3]);
                }
            } else {
                const float inv0 = __frcp_rn(sum0 + ss[r0]);
                const float inv1 = __frcp_rn(sum1 + ss[r1]);
                #pragma unroll
                for (int n = 0; n < 8; n++) {
                    const int col = 8 * n + 2 * tg;
                    float2 p0 = *reinterpret_cast<float2*>(op + r0 * D_FEAT + col);
                    float2 p1 = *reinterpret_cast<float2*>(op + r1 * D_FEAT + col);
                    *reinterpret_cast<float2*>(op + r0 * D_FEAT + col) =
                        make_float2((p0.x + O[n][0]) * inv0, (p0.y + O[n][1]) * inv0);
                    *reinterpret_cast<float2*>(op + r1 * D_FEAT + col) =
                        make_float2((p1.x + O[n][2]) * inv1, (p1.y + O[n][3]) * inv1);
                }
            }
        }
    }
}

extern "C" void kernel_launch(void* const* d_in, const int* in_sizes, int n_in,
                              void* d_out, int out_size)
{
    const float* x = (const float*)d_in[0];
    const float* centroids = (const float*)d_in[1];
    float* out = (float*)d_out;

    const int n_points = in_sizes[0] / D_FEAT;   // 131072
    const int n_tiles = n_points / TILE_M;       // 1024

    static bool attr_set = false;
    if (!attr_set) {
        cudaFuncSetAttribute(kmeans_hmma6_kernel,
                             cudaFuncAttributeMaxDynamicSharedMemorySize, SM_TOTAL);
        attr_set = true;
    }

    const int grid = (n_tiles < 148) ? n_tiles : 148;
    kmeans_hmma6_kernel<<<grid, NTHREADS, SM_TOTAL>>>(x, centroids, out, n_tiles);
}

// round 10
// speedup vs baseline: 1.0669x; 1.0669x over previous
#include <cuda_runtime.h>
#include <cuda_bf16.h>
#include <cstdint>

#define D_FEAT 64
#define TILE_M 128
#define NTHREADS 256
#define INV_T 10.0f
#define LOG2E 1.4426950408889634f
#define HALF_K 256
#define MAXTILES 7

// smem byte offsets
#define SM_G1 0            // GEMM1 B fragments, packed   64KB
#define SM_G2 65536        // GEMM2 B fragments, packed   64KB
#define SM_BIAS 131072     // 256 floats                  1KB
#define SM_SSUM 132096     // MAXTILES*128 floats         3.5KB
#define SM_TOTAL 135680

typedef unsigned int u32;

__device__ __forceinline__ u32 s2u(const void* p) {
    u32 a;
    asm("{ .reg .u64 t; cvta.to.shared.u64 t, %1; cvt.u32.u64 %0, t; }" : "=r"(a) : "l"(p));
    return a;
}
__device__ __forceinline__ void lds128(u32 addr, u32& q0, u32& q1, u32& q2, u32& q3) {
    asm volatile("ld.shared.v4.b32 {%0,%1,%2,%3}, [%4];"
                 : "=r"(q0), "=r"(q1), "=r"(q2), "=r"(q3) : "r"(addr));
}
__device__ __forceinline__ float ex2f(float v) {
    float y; asm("ex2.approx.ftz.f32 %0, %1;" : "=f"(y) : "f"(v)); return y;
}
// pack (lo, hi) -> bf16x2 with lo in low half
__device__ __forceinline__ u32 bf2(float lo, float hi) {
    u32 r; asm("cvt.rn.satfinite.bf16x2.f32 %0, %1, %2;" : "=r"(r) : "f"(hi), "f"(lo)); return r;
}
__device__ __forceinline__ float2 unbf2(u32 v) {
    __nv_bfloat162 b = *reinterpret_cast<__nv_bfloat162*>(&v);
    return make_float2(__bfloat162float(b.x), __bfloat162float(b.y));
}
// hi split + residual lo split
__device__ __forceinline__ u32 bf2r(float a, float b, u32& lo) {
    const u32 h = bf2(a, b);
    const float2 f = unbf2(h);
    lo = bf2(a - f.x, b - f.y);
    return h;
}
// D += A*B, m16n8k16 bf16 -> f32
__device__ __forceinline__ void mma16816(float* d, const u32* a, u32 b0, u32 b1) {
    asm volatile("mma.sync.aligned.m16n8k16.row.col.f32.bf16.bf16.f32 "
                 "{%0,%1,%2,%3}, {%4,%5,%6,%7}, {%8,%9}, {%0,%1,%2,%3};"
                 : "+f"(d[0]), "+f"(d[1]), "+f"(d[2]), "+f"(d[3])
                 : "r"(a[0]), "r"(a[1]), "r"(a[2]), "r"(a[3]), "r"(b0), "r"(b1));
}

// GEMM1 slice: one k-slice s, one 32-cluster half (4 n8 tiles) into S[4][4]
__device__ __forceinline__ void g1half(u32 g1b, int hidx, int s, float S[4][4],
                                       const u32 Ah[4][4], const u32 Al[4][4]) {
    const u32 base = g1b + (u32)(hidx >> 1) * 16384 + (u32)(hidx & 1) * 2048 + (u32)s * 4096;
    #pragma unroll
    for (int nb = 0; nb < 4; nb++) {
        u32 q0, q1, q2, q3;
        lds128(base + nb * 512, q0, q1, q2, q3);
        mma16816(S[nb], Ah[s], q0, q1);
        mma16816(S[nb], Ah[s], q2, q3);
        mma16816(S[nb], Al[s], q0, q1);
    }
}
// GEMM2 slice: one k16 slice (t within half) across all 8 feat n-tiles into O
__device__ __forceinline__ void g2half(u32 g2b, int hidx, int t, const u32 Wh[4],
                                       const u32 Wl[4], float O[8][4]) {
    const u32 base = g2b + (u32)(hidx >> 1) * 16384 + (u32)((hidx & 1) * 2 + t) * 4096;
    #pragma unroll
    for (int nb2 = 0; nb2 < 8; nb2++) {
        u32 q0, q1, q2, q3;
        lds128(base + nb2 * 512, q0, q1, q2, q3);
        mma16816(O[nb2], Wh, q0, q1);
        mma16816(O[nb2], Wh, q2, q3);
        mma16816(O[nb2], Wl, q0, q1);
    }
}

__global__ void __launch_bounds__(NTHREADS, 1)
kmeans_hmma7_kernel(const float* __restrict__ x,
                    const float* __restrict__ centroids,
                    float* __restrict__ out,
                    int n_tiles)
{
    extern __shared__ char smem[];
    const u32 sb = s2u(smem);
    const int tid = threadIdx.x;
    const int lane = tid & 31;
    const int wid = tid >> 5;
    const int gid = lane >> 2;
    const int tg = lane & 3;
    const int m0 = wid * 16;

    const float SC = 2.0f * INV_T * LOG2E;
    const u32 g1b = sb + SM_G1 + (u32)lane * 16;
    const u32 g2b = sb + SM_G2 + (u32)lane * 16;

    #pragma unroll 1
    for (int h = 0; h < 2; h++) {
        __syncthreads();
        // ---- build half h: fragment-packed B tables for both GEMMs + bias ----
        {
            const float4* C4 = reinterpret_cast<const float4*>(centroids) +
                               (size_t)h * HALF_K * (D_FEAT / 4);
            const float BSCALE = INV_T * LOG2E;
            #pragma unroll 1
            for (int it = 0; it < 16; it++) {
                const int i = tid + it * NTHREADS;     // 0..4095
                const float4 v = C4[i];
                const int cl = i >> 4;                 // local cluster 0..255
                const int dq = i & 15;                 // float4 index in row
                float vf[4] = {v.x, v.y, v.z, v.w};
                const int sub = cl >> 6, nb = (cl >> 3) & 7, gids = cl & 7;
                const int rr = cl & 63, t2 = rr >> 4, q2 = rr & 15;
                const int reg2 = (q2 >> 3) & 1, tgs2 = (q2 & 7) >> 1, el2 = q2 & 1;
                #pragma unroll
                for (int e = 0; e < 4; e++) {
                    const int d = 4 * dq + e;
                    u32 lo1;
                    const u32 hi1 = bf2r(vf[e], 0.f, lo1);
                    const __nv_bfloat162 H = *reinterpret_cast<const __nv_bfloat162*>(&hi1);
                    const __nv_bfloat162 L = *reinterpret_cast<const __nv_bfloat162*>(&lo1);
                    // G1: k = feat
                    {
                        const int s = d >> 4, r = d & 15;
                        const int reg = (r >> 3) & 1, tgs = (r & 7) >> 1, el = r & 1;
                        const u32 off = (u32)(((sub * 32 + s * 8 + nb) * 32 + gids * 4 + tgs) * 16
                                              + reg * 4 + el * 2);
                        *reinterpret_cast<__nv_bfloat16*>(smem + SM_G1 + off)     = H.x;
                        *reinterpret_cast<__nv_bfloat16*>(smem + SM_G1 + off + 8) = L.x;
                    }
                    // G2: k = cluster, n = feat
                    {
                        const int nb2 = d >> 3, gids2 = d & 7;
                        const u32 off = (u32)(((sub * 32 + t2 * 8 + nb2) * 32 + gids2 * 4 + tgs2) * 16
                                              + reg2 * 4 + el2 * 2);
                        *reinterpret_cast<__nv_bfloat16*>(smem + SM_G2 + off)     = H.x;
                        *reinterpret_cast<__nv_bfloat16*>(smem + SM_G2 + off + 8) = L.x;
                    }
                }
                float p = v.x * v.x + v.y * v.y + v.z * v.z + v.w * v.w;
                p += __shfl_xor_sync(0xFFFFFFFF, p, 1);
                p += __shfl_xor_sync(0xFFFFFFFF, p, 2);
                p += __shfl_xor_sync(0xFFFFFFFF, p, 4);
                p += __shfl_xor_sync(0xFFFFFFFF, p, 8);
                if ((lane & 15) == 0)
                    *reinterpret_cast<float*>(smem + SM_BIAS + cl * 4) = p * BSCALE;
            }
        }
        __syncthreads();

        // ---- tile loop ----
        int tloc = 0;
        #pragma unroll 1
        for (int tile = blockIdx.x; tile < n_tiles; tile += gridDim.x, tloc++) {
            // A fragments from gmem (PTX spec positions)
            u32 Ah[4][4], Al[4][4];
            {
                const float* xb = x + ((size_t)tile * TILE_M + m0 + gid) * D_FEAT;
                #pragma unroll
                for (int s = 0; s < 4; s++) {
                    const int c0 = 16 * s + 2 * tg;
                    const float2 v0 = *reinterpret_cast<const float2*>(xb + c0);
                    const float2 v1 = *reinterpret_cast<const float2*>(xb + 8 * D_FEAT + c0);
                    const float2 v2 = *reinterpret_cast<const float2*>(xb + c0 + 8);
                    const float2 v3 = *reinterpret_cast<const float2*>(xb + 8 * D_FEAT + c0 + 8);
                    Ah[s][0] = bf2r(v0.x, v0.y, Al[s][0]);
                    Ah[s][1] = bf2r(v1.x, v1.y, Al[s][1]);
                    Ah[s][2] = bf2r(v2.x, v2.y, Al[s][2]);
                    Ah[s][3] = bf2r(v3.x, v3.y, Al[s][3]);
                }
            }

            float O[8][4];
            #pragma unroll
            for (int n = 0; n < 8; n++)
                #pragma unroll
                for (int e = 0; e < 4; e++) O[n][e] = 0.f;
            float sum0 = 0.f, sum1 = 0.f;

            // double-buffered 32-cluster stages: S[2][4][4] = same reg count as
            // the old single 64-cluster S buffer
            float S[2][4][4];

            #define ZERO4(Sx)                                                       \
                { _Pragma("unroll") for (int nb = 0; nb < 4; nb++)                  \
                  { _Pragma("unroll") for (int e = 0; e < 4; e++) Sx[nb][e] = 0.f; } }
            // epilogue for a 32-cluster half
            #define EPI4(Sx, hidx)                                                  \
                { _Pragma("unroll") for (int nb = 0; nb < 4; nb++) {                \
                    const int coll = ((hidx) >> 1) * 64 + ((hidx) & 1) * 32 + nb * 8 + 2 * tg; \
                    const float2 bb = *reinterpret_cast<const float2*>(             \
                        smem + SM_BIAS + coll * 4);                                 \
                    Sx[nb][0] = ex2f(fmaf(Sx[nb][0], SC, -bb.x));                   \
                    Sx[nb][1] = ex2f(fmaf(Sx[nb][1], SC, -bb.y));                   \
                    Sx[nb][2] = ex2f(fmaf(Sx[nb][2], SC, -bb.x));                   \
                    Sx[nb][3] = ex2f(fmaf(Sx[nb][3], SC, -bb.y));                   \
                    sum0 += Sx[nb][0] + Sx[nb][1];                                  \
                    sum1 += Sx[nb][2] + Sx[nb][3];                                  \
                } }
            #define WSPLIT(Sx, t)                                                   \
                Wh[0] = bf2r(Sx[2*(t)][0],   Sx[2*(t)][1],   Wl[0]);                \
                Wh[1] = bf2r(Sx[2*(t)][2],   Sx[2*(t)][3],   Wl[1]);                \
                Wh[2] = bf2r(Sx[2*(t)+1][0], Sx[2*(t)+1][1], Wl[2]);                \
                Wh[3] = bf2r(Sx[2*(t)+1][2], Sx[2*(t)+1][3], Wl[3]);

            // pipeline prologue: fill stage 0
            ZERO4(S[0]);
            #pragma unroll
            for (int s = 0; s < 4; s++) g1half(g1b, 0, s, S[0], Ah, Al);

            #pragma unroll
            for (int i = 0; i < 8; i++) {
                const int cur = i & 1, nxt = cur ^ 1;
                u32 Wh[4], Wl[4];
                EPI4(S[cur], i);
                if (i < 7) ZERO4(S[nxt]);
                // t = 0: W-split, then next-stage GEMM1 (independent) + GEMM2
                WSPLIT(S[cur], 0);
                if (i < 7) {
                    g1half(g1b, i + 1, 0, S[nxt], Ah, Al);
                    g1half(g1b, i + 1, 1, S[nxt], Ah, Al);
                }
                g2half(g2b, i, 0, Wh, Wl, O);
                // t = 1
                WSPLIT(S[cur], 1);
                if (i < 7) {
                    g1half(g1b, i + 1, 2, S[nxt], Ah, Al);
                    g1half(g1b, i + 1, 3, S[nxt], Ah, Al);
                }
                g2half(g2b, i, 1, Wh, Wl, O);
            }
            #undef ZERO4
            #undef EPI4
            #undef WSPLIT

            // row sums across the 4 lanes of each row group
            sum0 += __shfl_xor_sync(0xFFFFFFFF, sum0, 1);
            sum0 += __shfl_xor_sync(0xFFFFFFFF, sum0, 2);
            sum1 += __shfl_xor_sync(0xFFFFFFFF, sum1, 1);
            sum1 += __shfl_xor_sync(0xFFFFFFFF, sum1, 2);

            float* op = out + ((size_t)tile * TILE_M) * D_FEAT;
            const int r0 = m0 + gid;
            const int r1 = r0 + 8;
            float* ss = reinterpret_cast<float*>(smem + SM_SSUM) + tloc * TILE_M;

            if (h == 0) {
                if (tg == 0) { ss[r0] = sum0; ss[r1] = sum1; }
                #pragma unroll
                for (int n = 0; n < 8; n++) {
                    const int col = 8 * n + 2 * tg;
                    *reinterpret_cast<float2*>(op + r0 * D_FEAT + col) = make_float2(O[n][0], O[n][1]);
                    *reinterpret_cast<float2*>(op + r1 * D_FEAT + col) = make_float2(O[n][2], O[n][3]);
                }
            } else {
                const float inv0 = __frcp_rn(sum0 + ss[r0]);
                const float inv1 = __frcp_rn(sum1 + ss[r1]);
                #pragma unroll
                for (int n = 0; n < 8; n++) {
                    const int col = 8 * n + 2 * tg;
                    float2 p0 = *reinterpret_cast<float2*>(op + r0 * D_FEAT + col);
                    float2 p1 = *reinterpret_cast<float2*>(op + r1 * D_FEAT + col);
                    *reinterpret_cast<float2*>(op + r0 * D_FEAT + col) =
                        make_float2((p0.x + O[n][0]) * inv0, (p0.y + O[n][1]) * inv0);
                    *reinterpret_cast<float2*>(op + r1 * D_FEAT + col) =
                        make_float2((p1.x + O[n][2]) * inv1, (p1.y + O[n][3]) * inv1);
                }
            }
        }
    }
}

extern "C" void kernel_launch(void* const* d_in, const int* in_sizes, int n_in,
                              void* d_out, int out_size)
{
    const float* x = (const float*)d_in[0];
    const float* centroids = (const float*)d_in[1];
    float* out = (float*)d_out;

    const int n_points = in_sizes[0] / D_FEAT;   // 131072
    const int n_tiles = n_points / TILE_M;       // 1024

    static bool attr_set = false;
    if (!attr_set) {
        cudaFuncSetAttribute(kmeans_hmma7_kernel,
                             cudaFuncAttributeMaxDynamicSharedMemorySize, SM_TOTAL);
        attr_set = true;
    }

    const int grid = (n_tiles < 148) ? n_tiles : 148;
    kmeans_hmma7_kernel<<<grid, NTHREADS, SM_TOTAL>>>(x, centroids, out, n_tiles);
}